// round 8
// baseline (speedup 1.0000x reference)
#include <cuda_runtime.h>
#include <math.h>

#define NB 16
#define NS 2048
#define NIN 128

typedef unsigned long long u64;
typedef unsigned int u32;

__device__ __forceinline__ u64 f2fma(u64 a, u64 b, u64 c) {
    u64 d; asm("fma.rn.f32x2 %0,%1,%2,%3;" : "=l"(d) : "l"(a), "l"(b), "l"(c)); return d;
}
__device__ __forceinline__ u64 f2add(u64 a, u64 b) {
    u64 d; asm("add.rn.f32x2 %0,%1,%2;" : "=l"(d) : "l"(a), "l"(b)); return d;
}
__device__ __forceinline__ u64 pk2(float x, float y) {
    u64 d; asm("mov.b64 %0,{%1,%2};" : "=l"(d) : "f"(x), "f"(y)); return d;
}
__device__ __forceinline__ float2 unpk(u64 v) {
    float2 r; asm("mov.b64 {%0,%1},%2;" : "=f"(r.x), "=f"(r.y) : "l"(v)); return r;
}
__device__ __forceinline__ void unpku(u64 v, u32& lo, u32& hi) {
    asm("mov.b64 {%0,%1},%2;" : "=r"(lo), "=r"(hi) : "l"(v));
}

// Scratch
__device__ float g_h0[NB * NS];
__device__ float g_h1[NB * NS];
__device__ float g_h2[NB * NS];
__device__ float g_cs[NB * NS];           // 0.5*|h|^2
__device__ ulonglong2 g_pp0[NB * NS / 2]; // row pairs: {(-h0_e,-h0_o),(-h1_e,-h1_o)}
__device__ ulonglong2 g_pp1[NB * NS / 2]; // row pairs: {(-h2_e,-h2_o),(cs_e, cs_o)}
__device__ int g_maxbits[NB];
__device__ unsigned int g_total[NB];
__device__ unsigned int g_det[NB];
__device__ unsigned int g_vert[NB];

// h = relu(x@w1+b1)@w2+b2 ; writes scalars + negated row-pair arrays.
__global__ __launch_bounds__(128) void k_embed(
    const float* __restrict__ x, const float* __restrict__ w1,
    const float* __restrict__ b1, const float* __restrict__ w2,
    const float* __restrict__ b2)
{
    if (blockIdx.x == 0 && threadIdx.x < NB) {
        g_maxbits[threadIdx.x] = 0;
        g_total[threadIdx.x] = 0u;
        g_det[threadIdx.x] = 0u;
        g_vert[threadIdx.x] = 0u;
    }

    __shared__ float s_w1[NIN * 6];
    __shared__ float s_w2[18];
    __shared__ float s_b1[6];
    __shared__ float s_b2[3];
    for (int i = threadIdx.x; i < NIN * 6; i += blockDim.x) s_w1[i] = w1[i];
    if (threadIdx.x < 18) s_w2[threadIdx.x] = w2[threadIdx.x];
    if (threadIdx.x < 6)  s_b1[threadIdx.x] = b1[threadIdx.x];
    if (threadIdx.x < 3)  s_b2[threadIdx.x] = b2[threadIdx.x];
    __syncthreads();

    int row = blockIdx.x * blockDim.x + threadIdx.x;
    if (row >= NB * NS) return;

    const float4* xr = (const float4*)(x + (size_t)row * NIN);
    float acc[6];
#pragma unroll
    for (int e = 0; e < 6; e++) acc[e] = s_b1[e];

#pragma unroll 16
    for (int q = 0; q < NIN / 4; q++) {
        float4 v = xr[q];
#pragma unroll
        for (int e = 0; e < 6; e++) {
            acc[e] = fmaf(v.x, s_w1[(4 * q + 0) * 6 + e], acc[e]);
            acc[e] = fmaf(v.y, s_w1[(4 * q + 1) * 6 + e], acc[e]);
            acc[e] = fmaf(v.z, s_w1[(4 * q + 2) * 6 + e], acc[e]);
            acc[e] = fmaf(v.w, s_w1[(4 * q + 3) * 6 + e], acc[e]);
        }
    }
#pragma unroll
    for (int e = 0; e < 6; e++) acc[e] = fmaxf(acc[e], 0.0f);

    float h0 = s_b2[0], h1 = s_b2[1], h2 = s_b2[2];
#pragma unroll
    for (int e = 0; e < 6; e++) {
        h0 = fmaf(acc[e], s_w2[e * 3 + 0], h0);
        h1 = fmaf(acc[e], s_w2[e * 3 + 1], h1);
        h2 = fmaf(acc[e], s_w2[e * 3 + 2], h2);
    }
    float cs = 0.5f * (h0 * h0 + h1 * h1 + h2 * h2);
    g_h0[row] = h0;
    g_h1[row] = h1;
    g_h2[row] = h2;
    g_cs[row] = cs;

    float h0n = __shfl_down_sync(0xffffffffu, h0, 1);
    float h1n = __shfl_down_sync(0xffffffffu, h1, 1);
    float h2n = __shfl_down_sync(0xffffffffu, h2, 1);
    float csn = __shfl_down_sync(0xffffffffu, cs, 1);
    if ((threadIdx.x & 1) == 0) {
        ulonglong2 a; a.x = pk2(-h0, -h0n); a.y = pk2(-h1, -h1n);
        ulonglong2 b; b.x = pk2(-h2, -h2n); b.y = pk2(cs, csn);
        g_pp0[row >> 1] = a;
        g_pp1[row >> 1] = b;
    }
}

// Pass 1: max of q = cs_r + cs_c - dot = d2/2, brute force, row-pair packed.
// 64-row x 512-col tiles; triangle cover = 80 tiles/batch.
__global__ __launch_bounds__(256, 6) void k_max() {
    int b = blockIdx.y;
    int xx = blockIdx.x;
    int rc, cc;
    if (xx < 32)      { cc = 3; rc = xx; }
    else if (xx < 56) { cc = 2; rc = xx - 32; }
    else if (xx < 72) { cc = 1; rc = xx - 56; }
    else              { cc = 0; rc = xx - 72; }
    int r0 = rc * 64;
    int tid = threadIdx.x;
    const int base = b * NS;
    const int pbase = (b * NS + r0) >> 1;

    __shared__ ulonglong2 sP0[32], sP1[32];
    if (tid < 32) {
        sP0[tid] = g_pp0[pbase + tid];
        sP1[tid] = g_pp1[pbase + tid];
    }
    __syncthreads();

    int cA = cc * 512 + tid;
    float tA0s = g_h0[base + cA], tB0s = g_h0[base + cA + 256];
    float tA1s = g_h1[base + cA], tB1s = g_h1[base + cA + 256];
    float tA2s = g_h2[base + cA], tB2s = g_h2[base + cA + 256];
    float dAs  = g_cs[base + cA], dBs  = g_cs[base + cA + 256];

    u64 tA0 = pk2(tA0s, tA0s), tA1 = pk2(tA1s, tA1s), tA2 = pk2(tA2s, tA2s), dA = pk2(dAs, dAs);
    u64 tB0 = pk2(tB0s, tB0s), tB1 = pk2(tB1s, tB1s), tB2 = pk2(tB2s, tB2s), dB = pk2(dBs, dBs);

    float mAx = 0.0f, mAy = 0.0f, mBx = 0.0f, mBy = 0.0f;
#pragma unroll 8
    for (int j = 0; j < 32; j++) {
        ulonglong2 P0 = sP0[j];
        ulonglong2 P1 = sP1[j];
        u64 qA = f2fma(P0.x, tA0, f2fma(P0.y, tA1, f2fma(P1.x, tA2, f2add(P1.y, dA))));
        u64 qB = f2fma(P0.x, tB0, f2fma(P0.y, tB1, f2fma(P1.x, tB2, f2add(P1.y, dB))));
        float2 fA = unpk(qA), fB = unpk(qB);
        mAx = fmaxf(mAx, fA.x);
        mAy = fmaxf(mAy, fA.y);
        mBx = fmaxf(mBx, fB.x);
        mBy = fmaxf(mBy, fB.y);
    }
    float m = fmaxf(fmaxf(mAx, mAy), fmaxf(mBx, mBy));

    __shared__ float red[256];
    red[tid] = m;
    __syncthreads();
    for (int o = 128; o > 0; o >>= 1) {
        if (tid < o) red[tid] = fmaxf(red[tid], red[tid + o]);
        __syncthreads();
    }
    if (tid == 0) atomicMax(&g_maxbits[b], __float_as_int(2.0f * red[0]));
}

// Super-diagonal band sum (offsets 1..9), shared-tiled. grid (8, NB).
__global__ __launch_bounds__(256) void k_det(const float* __restrict__ thp) {
    int b = blockIdx.y;
    int tid = threadIdx.x;
    int s0 = blockIdx.x * 256;
    const int base = b * NS;
    float th = *thp;
    float sig = 1.0f / (1.0f + expf(-th));
    float halfthr2 = 0.5f * sig * sig * __int_as_float(g_maxbits[b]);

    __shared__ float sh0[272], sh1[272], sh2[272], shc[272];
    int nrows = (s0 + 265 <= NS) ? 265 : (NS - s0);
    for (int i = tid; i < nrows; i += 256) {
        sh0[i] = g_h0[base + s0 + i];
        sh1[i] = g_h1[base + s0 + i];
        sh2[i] = g_h2[base + s0 + i];
        shc[i] = g_cs[base + s0 + i];
    }
    __syncthreads();

    unsigned int sum = 0;
    float h0 = sh0[tid], h1 = sh1[tid], h2 = sh2[tid];
    float cs = shc[tid] - halfthr2;
#pragma unroll
    for (int o = 1; o <= 9; o++) {
        int t = tid + o;
        if (s0 + t < NS) {
            float dot = fmaf(h0, sh0[t], fmaf(h1, sh1[t], h2 * sh2[t]));
            sum += (dot > (cs + shc[t])) ? 1u : 0u;
        }
    }
    __shared__ unsigned int red[256];
    red[tid] = sum;
    __syncthreads();
    for (int o = 128; o > 0; o >>= 1) {
        if (tid < o) red[tid] += red[tid + o];
        __syncthreads();
    }
    if (tid == 0) atomicAdd(&g_det[b], red[0]);
}

// Pass 2: total + vertical run-starts. Rows packed in f32x2 lanes; 2 cols/thread;
// one 32-bit word per column (1-bit shift run detection).
// 64 rows x 512 cols per block. grid: x = cb + 4*rc (cb 0..3, rc 0..31), y = batch.
__global__ __launch_bounds__(256, 5) void k_stats(const float* __restrict__ thp) {
    int xx = blockIdx.x;
    int cb = xx & 3;
    int rc = xx >> 2;
    int b = blockIdx.y;
    int r0 = rc * 64;
    int tid = threadIdx.x;
    const int base = b * NS;
    const int pbase = (b * NS + r0) >> 1;

    __shared__ ulonglong2 sP0[32], sP1[32];
    if (tid < 32) {
        sP0[tid] = g_pp0[pbase + tid];
        sP1[tid] = g_pp1[pbase + tid];
    }

    float th = *thp;
    float sig = 1.0f / (1.0f + expf(-th));
    float hth = 0.5f * sig * sig * __int_as_float(g_maxbits[b]);

    int cA = cb * 512 + tid;
    float tA0s = g_h0[base + cA], tB0s = g_h0[base + cA + 256];
    float tA1s = g_h1[base + cA], tB1s = g_h1[base + cA + 256];
    float tA2s = g_h2[base + cA], tB2s = g_h2[base + cA + 256];
    float dAs = g_cs[base + cA] - hth, dBs = g_cs[base + cA + 256] - hth;

    u64 tA0 = pk2(tA0s, tA0s), tA1 = pk2(tA1s, tA1s), tA2 = pk2(tA2s, tA2s), dA = pk2(dAs, dAs);
    u64 tB0 = pk2(tB0s, tB0s), tB1 = pk2(tB1s, tB1s), tB2 = pk2(tB2s, tB2s), dB = pk2(dBs, dBs);

#define SCBIT(rh0, rh1, rh2, rcs, t0s, t1s, t2s, ds)                              \
    (__float_as_uint(fmaf(-(rh0), (t0s), fmaf(-(rh1), (t1s),                      \
        fmaf(-(rh2), (t2s), (rcs) + (ds))))) >> 31)

    u32 pcA = 0, pcB = 0;   // R[r0-1]
    if (r0 > 0) {
        int r = base + r0 - 1;
        float rh0 = g_h0[r], rh1 = g_h1[r], rh2 = g_h2[r], rcs = g_cs[r];
        pcA = SCBIT(rh0, rh1, rh2, rcs, tA0s, tA1s, tA2s, dAs);
        pcB = SCBIT(rh0, rh1, rh2, rcs, tB0s, tB1s, tB2s, dBs);
    }
    u32 neA = 0, neB = 0;   // R[r0+64]
    if (r0 + 64 < NS) {
        int r = base + r0 + 64;
        float rh0 = g_h0[r], rh1 = g_h1[r], rh2 = g_h2[r], rcs = g_cs[r];
        neA = SCBIT(rh0, rh1, rh2, rcs, tA0s, tA1s, tA2s, dAs);
        neB = SCBIT(rh0, rh1, rh2, rcs, tB0s, tB1s, tB2s, dBs);
    }
    __syncthreads();

    u32 utot = 0, uvert = 0;
    u32 pendA = 0, pendB = 0;

#define PROCESS(pd, pc, nf)                                                      \
    {                                                                            \
        u32 prevw = (pd >> 1) | (pc << 31);                                      \
        u32 nextw = (pd << 1) | (nf);                                            \
        uvert += __popc(pd & ~prevw & nextw);                                    \
        utot += __popc(pd);                                                      \
        pc = pd & 1u;                                                            \
    }

#pragma unroll
    for (int wi = 0; wi < 2; wi++) {
        u32 wA = 0, wB = 0;
#pragma unroll
        for (int jj = 0; jj < 16; jj++) {
            int j = wi * 16 + jj;
            ulonglong2 P0 = sP0[j];
            ulonglong2 P1 = sP1[j];
            u64 qA = f2fma(P0.x, tA0, f2fma(P0.y, tA1, f2fma(P1.x, tA2, f2add(P1.y, dA))));
            u64 qB = f2fma(P0.x, tB0, f2fma(P0.y, tB1, f2fma(P1.x, tB2, f2add(P1.y, dB))));
            u32 lA, hA, lB, hB;
            unpku(qA, lA, hA);
            unpku(qB, lB, hB);
            wA = __funnelshift_l(lA, wA, 1);
            wA = __funnelshift_l(hA, wA, 1);
            wB = __funnelshift_l(lB, wB, 1);
            wB = __funnelshift_l(hB, wB, 1);
        }
        if (wi > 0) {
            u32 nfA = wA >> 31, nfB = wB >> 31;
            PROCESS(pendA, pcA, nfA);
            PROCESS(pendB, pcB, nfB);
        }
        pendA = wA;
        pendB = wB;
    }
    PROCESS(pendA, pcA, neA);
    PROCESS(pendB, pcB, neB);

#undef PROCESS
#undef SCBIT

    __shared__ unsigned int rt[256], rv[256];
    rt[tid] = utot;
    rv[tid] = uvert;
    __syncthreads();
    for (int o = 128; o > 0; o >>= 1) {
        if (tid < o) { rt[tid] += rt[tid + o]; rv[tid] += rv[tid + o]; }
        __syncthreads();
    }
    if (tid == 0) {
        atomicAdd(&g_total[b], rt[0]);
        atomicAdd(&g_vert[b], rv[0]);
    }
}

// Final: metrics [B,4] @ w3 [4,64] + b3 -> relu
__global__ __launch_bounds__(256) void k_final(
    const float* __restrict__ w3, const float* __restrict__ b3,
    float* __restrict__ out)
{
    int tid = blockIdx.x * blockDim.x + threadIdx.x;
    if (tid >= NB * 64) return;
    int b = tid >> 6;
    int j = tid & 63;

    float total = (float)g_total[b];
    float denom = total + 1e-6f;
    float rr = total * (1.0f / ((float)NS * (float)NS));
    float det = (float)g_det[b] / denom;
    float lam = (float)g_vert[b] / denom;
    float entr = -total * logf(1.0f + 1e-6f);

    float v = fmaf(rr, w3[j],
              fmaf(det, w3[64 + j],
              fmaf(lam, w3[128 + j],
              fmaf(entr, w3[192 + j], b3[j]))));
    out[tid] = fmaxf(v, 0.0f);
}

extern "C" void kernel_launch(void* const* d_in, const int* in_sizes, int n_in,
                              void* d_out, int out_size) {
    const float* x  = (const float*)d_in[0];
    const float* th = (const float*)d_in[1];
    const float* w1 = (const float*)d_in[2];
    const float* b1 = (const float*)d_in[3];
    const float* w2 = (const float*)d_in[4];
    const float* b2 = (const float*)d_in[5];
    const float* w3 = (const float*)d_in[6];
    const float* b3 = (const float*)d_in[7];
    float* out = (float*)d_out;

    k_embed<<<(NB * NS + 127) / 128, 128>>>(x, w1, b1, w2, b2);
    k_max<<<dim3(80, NB), 256>>>();
    k_det<<<dim3(8, NB), 256>>>(th);
    k_stats<<<dim3(128, NB), 256>>>(th);
    k_final<<<(NB * 64 + 255) / 256, 256>>>(w3, b3, out);
}